// round 6
// baseline (speedup 1.0000x reference)
#include <cuda_runtime.h>
#include <cuda_bf16.h>
#include <cstdint>

#define B_   16
#define N_   1024
#define DIN_ 256
#define H_   4
#define F_   64
#define OUT_ 256

// -------- scratch (device globals) --------
__device__ float    g_esrc[B_ * H_ * N_];
__device__ float    g_edst[B_ * H_ * N_];
// hT[b][hd][f][j] as bf16 pairs (uint32): hi and lo splits
__device__ uint32_t g_hT1[B_ * H_ * F_ * (N_ / 2)];
__device__ uint32_t g_hT2[B_ * H_ * F_ * (N_ / 2)];

// -------- f32x2 helpers (for gemm_h) --------
__device__ __forceinline__ unsigned long long pack2(float v) {
    unsigned long long r; unsigned int b = __float_as_uint(v);
    asm("mov.b64 %0, {%1, %1};" : "=l"(r) : "r"(b)); return r;
}
__device__ __forceinline__ unsigned long long fma2(unsigned long long a,
                                                   unsigned long long b,
                                                   unsigned long long c) {
    unsigned long long d;
    asm("fma.rn.f32x2 %0, %1, %2, %3;" : "=l"(d) : "l"(a), "l"(b), "l"(c));
    return d;
}
__device__ __forceinline__ float2 unpack2(unsigned long long v) {
    unsigned int lo, hi;
    asm("mov.b64 {%0, %1}, %2;" : "=r"(lo), "=r"(hi) : "l"(v));
    return make_float2(__uint_as_float(lo), __uint_as_float(hi));
}

// bf16 split helpers
__device__ __forceinline__ uint32_t hi_pack(float v0, float v1) {
    uint32_t r;
    asm("prmt.b32 %0, %1, %2, 0x7632;" : "=r"(r)
        : "r"(__float_as_uint(v0)), "r"(__float_as_uint(v1)));
    return r;   // low half = trunc-bf16(v0), high = trunc-bf16(v1)
}
__device__ __forceinline__ uint32_t lo_pack(float v0, float v1) {
    float l0 = v0 - __uint_as_float(__float_as_uint(v0) & 0xFFFF0000u);
    float l1 = v1 - __uint_as_float(__float_as_uint(v1) & 0xFFFF0000u);
    uint32_t r;
    asm("cvt.rn.bf16x2.f32 %0, %1, %2;" : "=r"(r) : "f"(l1), "f"(l0));
    return r;   // low half = bf16(residual v0)
}

// warp-level bf16 MMA (HMMA path, sm_80+; no sm_103a-only features)
__device__ __forceinline__ void mma16816(float* c, uint32_t a0, uint32_t a1,
                                         uint32_t a2, uint32_t a3,
                                         uint32_t b0, uint32_t b1) {
    asm volatile(
        "mma.sync.aligned.m16n8k16.row.col.f32.bf16.bf16.f32 "
        "{%0,%1,%2,%3}, {%4,%5,%6,%7}, {%8,%9}, {%0,%1,%2,%3};"
        : "+f"(c[0]), "+f"(c[1]), "+f"(c[2]), "+f"(c[3])
        : "r"(a0), "r"(a1), "r"(a2), "r"(a3), "r"(b0), "r"(b1));
}

// ============================================================================
// Kernel 1: h = x @ W (64 rows x one head). Outputs hT hi/lo bf16 + esrc/edst.
// ============================================================================
__global__ __launch_bounds__(256) void gemm_h_kernel(
    const float* __restrict__ x, const float* __restrict__ W,
    const float* __restrict__ a_src, const float* __restrict__ a_dst)
{
    __shared__ float As[16 * 65];
    __shared__ float Bs[16 * 64];
    __shared__ float h_t[64 * 65];   // [f][n_local] transpose staging

    const int head = blockIdx.x;
    const int m0   = blockIdx.y * 64;
    const int tid  = threadIdx.x;
    const int ty   = tid >> 4;
    const int tx   = tid & 15;

    unsigned long long acc[4][2];
#pragma unroll
    for (int i = 0; i < 4; i++) { acc[i][0] = 0ull; acc[i][1] = 0ull; }

    const int lrow = tid >> 2, lk4 = tid & 3;
    const int bk   = tid >> 4, bn4 = tid & 15;

    for (int k0 = 0; k0 < DIN_; k0 += 16) {
        __syncthreads();
        float4 xa = *(const float4*)(x + (size_t)(m0 + lrow) * DIN_ + k0 + lk4 * 4);
        As[(lk4 * 4 + 0) * 65 + lrow] = xa.x;
        As[(lk4 * 4 + 1) * 65 + lrow] = xa.y;
        As[(lk4 * 4 + 2) * 65 + lrow] = xa.z;
        As[(lk4 * 4 + 3) * 65 + lrow] = xa.w;
        *(float4*)(Bs + bk * 64 + bn4 * 4) =
            *(const float4*)(W + (size_t)(k0 + bk) * OUT_ + head * 64 + bn4 * 4);
        __syncthreads();
#pragma unroll
        for (int k = 0; k < 16; k++) {
            ulonglong2 bv = ((const ulonglong2*)(Bs + k * 64))[tx];
#pragma unroll
            for (int ri = 0; ri < 4; ri++) {
                unsigned long long a2 = pack2(As[k * 65 + ty + 16 * ri]);
                acc[ri][0] = fma2(a2, bv.x, acc[ri][0]);
                acc[ri][1] = fma2(a2, bv.y, acc[ri][1]);
            }
        }
    }

    const int b  = m0 >> 10;
    const int nb = m0 & (N_ - 1);
    float4 asv = *(const float4*)(a_src + head * 64 + tx * 4);
    float4 adv = *(const float4*)(a_dst + head * 64 + tx * 4);

    __syncthreads();
#pragma unroll
    for (int ri = 0; ri < 4; ri++) {
        int row = ty + 16 * ri;
        float2 p0 = unpack2(acc[ri][0]);
        float2 p1 = unpack2(acc[ri][1]);
        h_t[(tx * 4 + 0) * 65 + row] = p0.x;
        h_t[(tx * 4 + 1) * 65 + row] = p0.y;
        h_t[(tx * 4 + 2) * 65 + row] = p1.x;
        h_t[(tx * 4 + 3) * 65 + row] = p1.y;
        float ssrc = p0.x * asv.x + p0.y * asv.y + p1.x * asv.z + p1.y * asv.w;
        float sdst = p0.x * adv.x + p0.y * adv.y + p1.x * adv.z + p1.y * adv.w;
#pragma unroll
        for (int off = 8; off >= 1; off >>= 1) {
            ssrc += __shfl_down_sync(0xffffffffu, ssrc, off, 16);
            sdst += __shfl_down_sync(0xffffffffu, sdst, off, 16);
        }
        if (tx == 0) {
            g_esrc[(b * H_ + head) * N_ + nb + row] = ssrc;
            g_edst[(b * H_ + head) * N_ + nb + row] = sdst;
        }
    }
    __syncthreads();

    // write hT hi/lo: thread -> f = tid>>2, 16 n values
    {
        const int f  = tid >> 2;
        const int nq = (tid & 3) * 16;
        const float* row = &h_t[f * 65 + nq];
        uint32_t hi[8], lo[8];
#pragma unroll
        for (int k = 0; k < 8; k++) {
            hi[k] = hi_pack(row[2 * k], row[2 * k + 1]);
            lo[k] = lo_pack(row[2 * k], row[2 * k + 1]);
        }
        size_t bi = ((size_t)(b * H_ + head) * F_ + f) * (N_ / 2) + (nb + nq) / 2;
        *(uint4*)&g_hT1[bi]     = make_uint4(hi[0], hi[1], hi[2], hi[3]);
        *(uint4*)&g_hT1[bi + 4] = make_uint4(hi[4], hi[5], hi[6], hi[7]);
        *(uint4*)&g_hT2[bi]     = make_uint4(lo[0], lo[1], lo[2], lo[3]);
        *(uint4*)&g_hT2[bi + 4] = make_uint4(lo[4], lo[5], lo[6], lo[7]);
    }
}

// ============================================================================
// Kernel 2: HMMA flash-GAT. CTA = (b, 128 i-rows), all 4 heads, 8 warps.
// Warp w owns i-rows w*16..+15. A (softmax P) fragments computed directly in
// registers (never hits smem); B = hT hi/lo bf16 in smem, conflict-free.
// 3-term split-bf16 mma: A1*B1 + A1*B2 + A2*B1.
// ============================================================================
#define HB_STR 68   // uint32 row stride for B smem: bank = (4f + c) mod 32, conflict-free

__global__ __launch_bounds__(256, 1) void gat_attn_mma_kernel(
    const float* __restrict__ adj, const float* __restrict__ bias,
    float* __restrict__ out)
{
    __shared__ uint32_t abits[128][4];       // adjacency bitmask, 2 KB
    __shared__ float    es_sh[H_][128];      // e_src tile per head
    __shared__ float    ed_sh[H_][128];      // e_dst per head (whole CTA rows)
    __shared__ uint32_t hb1[64 * HB_STR];    // B hi split
    __shared__ uint32_t hb2[64 * HB_STR];    // B lo split

    const int tid = threadIdx.x;
    const int wid = tid >> 5;
    const int l   = tid & 31;
    const int q   = l >> 2;     // row-in-tile 0..7
    const int c   = l & 3;      // col group
    const int b   = blockIdx.y;
    const int i0  = blockIdx.x * 128;

    // e_dst for all heads (once)
    for (int idx = tid; idx < H_ * 128; idx += 256)
        ed_sh[idx >> 7][idx & 127] = g_edst[(b * H_ + (idx >> 7)) * N_ + i0 + (idx & 127)];

    float acc[H_][8][4];
    float den[H_][2];
#pragma unroll
    for (int hd = 0; hd < H_; hd++) {
        den[hd][0] = 0.f; den[hd][1] = 0.f;
#pragma unroll
        for (int nt = 0; nt < 8; nt++)
#pragma unroll
            for (int k = 0; k < 4; k++) acc[hd][nt][k] = 0.f;
    }

    const float* adj_b = adj + (size_t)b * N_ * N_;

    for (int chunk = 0; chunk < 8; chunk++) {
        const int j0 = chunk * 128;
        __syncthreads();   // protect abits/es from previous-chunk readers

        // adjacency bitmask: warp w handles its own 16 rows
#pragma unroll 4
        for (int k = 0; k < 16; k++) {
            int r = wid * 16 + k;
            const float* arow = adj_b + (size_t)(i0 + r) * N_ + j0;
#pragma unroll
            for (int jg = 0; jg < 4; jg++) {
                uint32_t m = __ballot_sync(0xffffffffu, arow[jg * 32 + l] > 0.5f);
                if (l == 0) abits[r][jg] = m;
            }
        }
        // e_src tile (all heads)
        for (int idx = tid; idx < H_ * 128; idx += 256)
            es_sh[idx >> 7][idx & 127] =
                g_esrc[(b * H_ + (idx >> 7)) * N_ + j0 + (idx & 127)];

#pragma unroll
        for (int hd = 0; hd < H_; hd++) {
            __syncthreads();   // abits/es ready (hd=0) / prev-head mma done (hd>0)
            // load B tiles hi/lo for this head
            {
                const size_t gbase = ((size_t)(b * H_ + hd) * F_) * (N_ / 2) + (j0 >> 1);
                const int f = tid >> 2, cw = (tid & 3) * 16;
#pragma unroll
                for (int t = 0; t < 4; t++) {
                    *(uint4*)&hb1[f * HB_STR + cw + t * 4] =
                        *(const uint4*)&g_hT1[gbase + (size_t)f * (N_ / 2) + cw + t * 4];
                    *(uint4*)&hb2[f * HB_STR + cw + t * 4] =
                        *(const uint4*)&g_hT2[gbase + (size_t)f * (N_ / 2) + cw + t * 4];
                }
            }
            __syncthreads();

            // per-warp fused P-fragment compute + mma
            const int r0 = wid * 16 + q;      // local rows r0, r0+8
            const float ed0 = ed_sh[hd][r0];
            const float ed1 = ed_sh[hd][r0 + 8];
            uint32_t ar0[4], ar1[4];
#pragma unroll
            for (int w = 0; w < 4; w++) { ar0[w] = abits[r0][w]; ar1[w] = abits[r0 + 8][w]; }

            float dsum0 = 0.f, dsum1 = 0.f;
#pragma unroll
            for (int kt = 0; kt < 8; kt++) {
                const int jA = kt * 16 + c * 2;
                float2 eA = *(const float2*)&es_sh[hd][jA];
                float2 eB = *(const float2*)&es_sh[hd][jA + 8];
                const uint32_t w0 = ar0[kt >> 1], w1 = ar1[kt >> 1];
                const int bb = ((kt & 1) << 4) + c * 2;

                float p00, p01, p08, p09, p10, p11, p18, p19;
                {
                    float s;
                    s = ed0 + eA.x; s = fmaxf(s, 0.2f * s); p00 = ((w0 >> bb) & 1u) ? __expf(s) : 0.f;
                    s = ed0 + eA.y; s = fmaxf(s, 0.2f * s); p01 = ((w0 >> (bb + 1)) & 1u) ? __expf(s) : 0.f;
                    s = ed0 + eB.x; s = fmaxf(s, 0.2f * s); p08 = ((w0 >> (bb + 8)) & 1u) ? __expf(s) : 0.f;
                    s = ed0 + eB.y; s = fmaxf(s, 0.2f * s); p09 = ((w0 >> (bb + 9)) & 1u) ? __expf(s) : 0.f;
                    s = ed1 + eA.x; s = fmaxf(s, 0.2f * s); p10 = ((w1 >> bb) & 1u) ? __expf(s) : 0.f;
                    s = ed1 + eA.y; s = fmaxf(s, 0.2f * s); p11 = ((w1 >> (bb + 1)) & 1u) ? __expf(s) : 0.f;
                    s = ed1 + eB.x; s = fmaxf(s, 0.2f * s); p18 = ((w1 >> (bb + 8)) & 1u) ? __expf(s) : 0.f;
                    s = ed1 + eB.y; s = fmaxf(s, 0.2f * s); p19 = ((w1 >> (bb + 9)) & 1u) ? __expf(s) : 0.f;
                }
                dsum0 += (p00 + p01) + (p08 + p09);
                dsum1 += (p10 + p11) + (p18 + p19);

                const uint32_t a0h = hi_pack(p00, p01), a1h = hi_pack(p10, p11);
                const uint32_t a2h = hi_pack(p08, p09), a3h = hi_pack(p18, p19);
                const uint32_t a0l = lo_pack(p00, p01), a1l = lo_pack(p10, p11);
                const uint32_t a2l = lo_pack(p08, p09), a3l = lo_pack(p18, p19);

#pragma unroll
                for (int nt = 0; nt < 8; nt++) {
                    const int bidx = (nt * 8 + q) * HB_STR + kt * 8 + c;
                    const uint32_t b10 = hb1[bidx], b11 = hb1[bidx + 4];
                    const uint32_t b20 = hb2[bidx], b21 = hb2[bidx + 4];
                    mma16816(acc[hd][nt], a0h, a1h, a2h, a3h, b10, b11);
                    mma16816(acc[hd][nt], a0h, a1h, a2h, a3h, b20, b21);
                    mma16816(acc[hd][nt], a0l, a1l, a2l, a3l, b10, b11);
                }
            }
            den[hd][0] += dsum0;
            den[hd][1] += dsum1;
        }
    }

    // ---- epilogue: out = acc / den + bias ----
    const int gr0 = b * N_ + i0 + wid * 16 + q;
#pragma unroll
    for (int hd = 0; hd < H_; hd++) {
        float d0 = den[hd][0];
        d0 += __shfl_xor_sync(0xffffffffu, d0, 1);
        d0 += __shfl_xor_sync(0xffffffffu, d0, 2);
        float d1 = den[hd][1];
        d1 += __shfl_xor_sync(0xffffffffu, d1, 1);
        d1 += __shfl_xor_sync(0xffffffffu, d1, 2);
        const float rl0 = 1.0f / d0, rl1 = 1.0f / d1;
#pragma unroll
        for (int nt = 0; nt < 8; nt++) {
            const int col = hd * 64 + nt * 8 + c * 2;
            float2 bv = __ldg((const float2*)(bias + col));
            float2 o0, o1;
            o0.x = acc[hd][nt][0] * rl0 + bv.x;
            o0.y = acc[hd][nt][1] * rl0 + bv.y;
            o1.x = acc[hd][nt][2] * rl1 + bv.x;
            o1.y = acc[hd][nt][3] * rl1 + bv.y;
            *(float2*)(out + (size_t)gr0 * OUT_ + col)       = o0;
            *(float2*)(out + (size_t)(gr0 + 8) * OUT_ + col) = o1;
        }
    }
}

// ============================================================================
extern "C" void kernel_launch(void* const* d_in, const int* in_sizes, int n_in,
                              void* d_out, int out_size)
{
    const float* x     = (const float*)d_in[0];
    const float* adj   = (const float*)d_in[1];
    const float* W     = (const float*)d_in[2];
    const float* a_src = (const float*)d_in[3];
    const float* a_dst = (const float*)d_in[4];
    const float* bias  = (const float*)d_in[5];
    float* out = (float*)d_out;

    gemm_h_kernel<<<dim3(H_, (B_ * N_) / 64), 256>>>(x, W, a_src, a_dst);
    gat_attn_mma_kernel<<<dim3(N_ / 128, B_), 256>>>(adj, bias, out);
}

// round 8
// speedup vs baseline: 1.8909x; 1.8909x over previous
#include <cuda_runtime.h>
#include <cuda_bf16.h>
#include <cstdint>

#define B_   16
#define N_   1024
#define DIN_ 256
#define H_   4
#define F_   64
#define OUT_ 256

// -------- scratch (device globals) --------
__device__ float    g_esrc[B_ * H_ * N_];
__device__ float    g_edst[B_ * H_ * N_];
// hT[b][hd][f][j] as bf16 pairs (uint32): hi and lo splits
__device__ uint32_t g_hT1[B_ * H_ * F_ * (N_ / 2)];
__device__ uint32_t g_hT2[B_ * H_ * F_ * (N_ / 2)];

// -------- f32x2 helpers (for gemm_h) --------
__device__ __forceinline__ unsigned long long pack2(float v) {
    unsigned long long r; unsigned int b = __float_as_uint(v);
    asm("mov.b64 %0, {%1, %1};" : "=l"(r) : "r"(b)); return r;
}
__device__ __forceinline__ unsigned long long fma2(unsigned long long a,
                                                   unsigned long long b,
                                                   unsigned long long c) {
    unsigned long long d;
    asm("fma.rn.f32x2 %0, %1, %2, %3;" : "=l"(d) : "l"(a), "l"(b), "l"(c));
    return d;
}
__device__ __forceinline__ float2 unpack2(unsigned long long v) {
    unsigned int lo, hi;
    asm("mov.b64 {%0, %1}, %2;" : "=r"(lo), "=r"(hi) : "l"(v));
    return make_float2(__uint_as_float(lo), __uint_as_float(hi));
}

// bf16 split helpers
__device__ __forceinline__ uint32_t hi_pack(float v0, float v1) {
    uint32_t r;
    asm("prmt.b32 %0, %1, %2, 0x7632;" : "=r"(r)
        : "r"(__float_as_uint(v0)), "r"(__float_as_uint(v1)));
    return r;
}
__device__ __forceinline__ uint32_t lo_pack(float v0, float v1) {
    float l0 = v0 - __uint_as_float(__float_as_uint(v0) & 0xFFFF0000u);
    float l1 = v1 - __uint_as_float(__float_as_uint(v1) & 0xFFFF0000u);
    uint32_t r;
    asm("cvt.rn.bf16x2.f32 %0, %1, %2;" : "=r"(r) : "f"(l1), "f"(l0));
    return r;
}

// warp-level bf16 MMA (HMMA path, sm_80+)
__device__ __forceinline__ void mma16816(float* c, uint32_t a0, uint32_t a1,
                                         uint32_t a2, uint32_t a3,
                                         uint32_t b0, uint32_t b1) {
    asm volatile(
        "mma.sync.aligned.m16n8k16.row.col.f32.bf16.bf16.f32 "
        "{%0,%1,%2,%3}, {%4,%5,%6,%7}, {%8,%9}, {%0,%1,%2,%3};"
        : "+f"(c[0]), "+f"(c[1]), "+f"(c[2]), "+f"(c[3])
        : "r"(a0), "r"(a1), "r"(a2), "r"(a3), "r"(b0), "r"(b1));
}

// ============================================================================
// Kernel 1: h = x @ W (64 rows x one head). Outputs hT hi/lo bf16 + esrc/edst.
// ============================================================================
__global__ __launch_bounds__(256) void gemm_h_kernel(
    const float* __restrict__ x, const float* __restrict__ W,
    const float* __restrict__ a_src, const float* __restrict__ a_dst)
{
    __shared__ float As[16 * 65];
    __shared__ float Bs[16 * 64];
    __shared__ float h_t[64 * 65];

    const int head = blockIdx.x;
    const int m0   = blockIdx.y * 64;
    const int tid  = threadIdx.x;
    const int ty   = tid >> 4;
    const int tx   = tid & 15;

    unsigned long long acc[4][2];
#pragma unroll
    for (int i = 0; i < 4; i++) { acc[i][0] = 0ull; acc[i][1] = 0ull; }

    const int lrow = tid >> 2, lk4 = tid & 3;
    const int bk   = tid >> 4, bn4 = tid & 15;

    for (int k0 = 0; k0 < DIN_; k0 += 16) {
        __syncthreads();
        float4 xa = *(const float4*)(x + (size_t)(m0 + lrow) * DIN_ + k0 + lk4 * 4);
        As[(lk4 * 4 + 0) * 65 + lrow] = xa.x;
        As[(lk4 * 4 + 1) * 65 + lrow] = xa.y;
        As[(lk4 * 4 + 2) * 65 + lrow] = xa.z;
        As[(lk4 * 4 + 3) * 65 + lrow] = xa.w;
        *(float4*)(Bs + bk * 64 + bn4 * 4) =
            *(const float4*)(W + (size_t)(k0 + bk) * OUT_ + head * 64 + bn4 * 4);
        __syncthreads();
#pragma unroll
        for (int k = 0; k < 16; k++) {
            ulonglong2 bv = ((const ulonglong2*)(Bs + k * 64))[tx];
#pragma unroll
            for (int ri = 0; ri < 4; ri++) {
                unsigned long long a2 = pack2(As[k * 65 + ty + 16 * ri]);
                acc[ri][0] = fma2(a2, bv.x, acc[ri][0]);
                acc[ri][1] = fma2(a2, bv.y, acc[ri][1]);
            }
        }
    }

    const int b  = m0 >> 10;
    const int nb = m0 & (N_ - 1);
    float4 asv = *(const float4*)(a_src + head * 64 + tx * 4);
    float4 adv = *(const float4*)(a_dst + head * 64 + tx * 4);

    __syncthreads();
#pragma unroll
    for (int ri = 0; ri < 4; ri++) {
        int row = ty + 16 * ri;
        float2 p0 = unpack2(acc[ri][0]);
        float2 p1 = unpack2(acc[ri][1]);
        h_t[(tx * 4 + 0) * 65 + row] = p0.x;
        h_t[(tx * 4 + 1) * 65 + row] = p0.y;
        h_t[(tx * 4 + 2) * 65 + row] = p1.x;
        h_t[(tx * 4 + 3) * 65 + row] = p1.y;
        float ssrc = p0.x * asv.x + p0.y * asv.y + p1.x * asv.z + p1.y * asv.w;
        float sdst = p0.x * adv.x + p0.y * adv.y + p1.x * adv.z + p1.y * adv.w;
#pragma unroll
        for (int off = 8; off >= 1; off >>= 1) {
            ssrc += __shfl_down_sync(0xffffffffu, ssrc, off, 16);
            sdst += __shfl_down_sync(0xffffffffu, sdst, off, 16);
        }
        if (tx == 0) {
            g_esrc[(b * H_ + head) * N_ + nb + row] = ssrc;
            g_edst[(b * H_ + head) * N_ + nb + row] = sdst;
        }
    }
    __syncthreads();

    {
        const int f  = tid >> 2;
        const int nq = (tid & 3) * 16;
        const float* row = &h_t[f * 65 + nq];
        uint32_t hi[8], lo[8];
#pragma unroll
        for (int k = 0; k < 8; k++) {
            hi[k] = hi_pack(row[2 * k], row[2 * k + 1]);
            lo[k] = lo_pack(row[2 * k], row[2 * k + 1]);
        }
        size_t bi = ((size_t)(b * H_ + head) * F_ + f) * (N_ / 2) + (nb + nq) / 2;
        *(uint4*)&g_hT1[bi]     = make_uint4(hi[0], hi[1], hi[2], hi[3]);
        *(uint4*)&g_hT1[bi + 4] = make_uint4(hi[4], hi[5], hi[6], hi[7]);
        *(uint4*)&g_hT2[bi]     = make_uint4(lo[0], lo[1], lo[2], lo[3]);
        *(uint4*)&g_hT2[bi + 4] = make_uint4(lo[4], lo[5], lo[6], lo[7]);
    }
}

// ============================================================================
// Kernel 2: HMMA flash-GAT, head-split for occupancy (re-run of R7; R7 bench
// was an infra failure with no kernel-attributable cause).
// CTA = (b, 128 i-rows, 2 heads); grid.z = 2 head-pairs; 8 warps.
// ============================================================================
#define HB_STR 68   // uint32 row stride: bank = (4f + c) mod 32, conflict-free

__global__ __launch_bounds__(256, 2) void gat_attn_mma_kernel(
    const float* __restrict__ adj, const float* __restrict__ bias,
    float* __restrict__ out)
{
    __shared__ uint32_t abits[128][4];
    __shared__ float    es_sh[2][128];
    __shared__ float    ed_sh[2][128];
    __shared__ uint32_t hb1[64 * HB_STR];
    __shared__ uint32_t hb2[64 * HB_STR];

    const int tid = threadIdx.x;
    const int wid = tid >> 5;
    const int l   = tid & 31;
    const int q   = l >> 2;
    const int c   = l & 3;
    const int b   = blockIdx.y;
    const int i0  = blockIdx.x * 128;
    const int hp  = blockIdx.z;          // head pair: heads hp*2, hp*2+1

    for (int idx = tid; idx < 2 * 128; idx += 256)
        ed_sh[idx >> 7][idx & 127] =
            g_edst[(b * H_ + hp * 2 + (idx >> 7)) * N_ + i0 + (idx & 127)];

    float acc[2][8][4];
    float den[2][2];
#pragma unroll
    for (int hh = 0; hh < 2; hh++) {
        den[hh][0] = 0.f; den[hh][1] = 0.f;
#pragma unroll
        for (int nt = 0; nt < 8; nt++)
#pragma unroll
            for (int k = 0; k < 4; k++) acc[hh][nt][k] = 0.f;
    }

    const float* adj_b = adj + (size_t)b * N_ * N_;

    for (int chunk = 0; chunk < 8; chunk++) {
        const int j0 = chunk * 128;
        __syncthreads();

        // adjacency bitmask: warp w handles its own 16 rows
#pragma unroll 4
        for (int k = 0; k < 16; k++) {
            int r = wid * 16 + k;
            const float* arow = adj_b + (size_t)(i0 + r) * N_ + j0;
#pragma unroll
            for (int jg = 0; jg < 4; jg++) {
                uint32_t m = __ballot_sync(0xffffffffu, arow[jg * 32 + l] > 0.5f);
                if (l == 0) abits[r][jg] = m;
            }
        }
        for (int idx = tid; idx < 2 * 128; idx += 256)
            es_sh[idx >> 7][idx & 127] =
                g_esrc[(b * H_ + hp * 2 + (idx >> 7)) * N_ + j0 + (idx & 127)];

#pragma unroll
        for (int hh = 0; hh < 2; hh++) {
            __syncthreads();
            // load B tiles hi/lo for this head
            {
                const size_t gbase =
                    ((size_t)(b * H_ + hp * 2 + hh) * F_) * (N_ / 2) + (j0 >> 1);
                const int f = tid >> 2, cw = (tid & 3) * 16;
#pragma unroll
                for (int t = 0; t < 4; t++) {
                    *(uint4*)&hb1[f * HB_STR + cw + t * 4] =
                        *(const uint4*)&g_hT1[gbase + (size_t)f * (N_ / 2) + cw + t * 4];
                    *(uint4*)&hb2[f * HB_STR + cw + t * 4] =
                        *(const uint4*)&g_hT2[gbase + (size_t)f * (N_ / 2) + cw + t * 4];
                }
            }
            __syncthreads();

            const int r0 = wid * 16 + q;
            const float ed0 = ed_sh[hh][r0];
            const float ed1 = ed_sh[hh][r0 + 8];
            float dsum0 = 0.f, dsum1 = 0.f;
#pragma unroll
            for (int kt = 0; kt < 8; kt++) {
                const int jA = kt * 16 + c * 2;
                float2 eA = *(const float2*)&es_sh[hh][jA];
                float2 eB = *(const float2*)&es_sh[hh][jA + 8];
                const uint32_t w0 = abits[r0][kt >> 1];
                const uint32_t w1 = abits[r0 + 8][kt >> 1];
                const int bb = ((kt & 1) << 4) + c * 2;

                float p00, p01, p08, p09, p10, p11, p18, p19;
                {
                    float s;
                    s = ed0 + eA.x; s = fmaxf(s, 0.2f * s); p00 = ((w0 >> bb) & 1u) ? __expf(s) : 0.f;
                    s = ed0 + eA.y; s = fmaxf(s, 0.2f * s); p01 = ((w0 >> (bb + 1)) & 1u) ? __expf(s) : 0.f;
                    s = ed0 + eB.x; s = fmaxf(s, 0.2f * s); p08 = ((w0 >> (bb + 8)) & 1u) ? __expf(s) : 0.f;
                    s = ed0 + eB.y; s = fmaxf(s, 0.2f * s); p09 = ((w0 >> (bb + 9)) & 1u) ? __expf(s) : 0.f;
                    s = ed1 + eA.x; s = fmaxf(s, 0.2f * s); p10 = ((w1 >> bb) & 1u) ? __expf(s) : 0.f;
                    s = ed1 + eA.y; s = fmaxf(s, 0.2f * s); p11 = ((w1 >> (bb + 1)) & 1u) ? __expf(s) : 0.f;
                    s = ed1 + eB.x; s = fmaxf(s, 0.2f * s); p18 = ((w1 >> (bb + 8)) & 1u) ? __expf(s) : 0.f;
                    s = ed1 + eB.y; s = fmaxf(s, 0.2f * s); p19 = ((w1 >> (bb + 9)) & 1u) ? __expf(s) : 0.f;
                }
                dsum0 += (p00 + p01) + (p08 + p09);
                dsum1 += (p10 + p11) + (p18 + p19);

                const uint32_t a0h = hi_pack(p00, p01), a1h = hi_pack(p10, p11);
                const uint32_t a2h = hi_pack(p08, p09), a3h = hi_pack(p18, p19);
                const uint32_t a0l = lo_pack(p00, p01), a1l = lo_pack(p10, p11);
                const uint32_t a2l = lo_pack(p08, p09), a3l = lo_pack(p18, p19);

#pragma unroll
                for (int nt = 0; nt < 8; nt++) {
                    const int bidx = (nt * 8 + q) * HB_STR + kt * 8 + c;
                    const uint32_t b10 = hb1[bidx], b11 = hb1[bidx + 4];
                    const uint32_t b20 = hb2[bidx], b21 = hb2[bidx + 4];
                    mma16816(acc[hh][nt], a0h, a1h, a2h, a3h, b10, b11);
                    mma16816(acc[hh][nt], a0h, a1h, a2h, a3h, b20, b21);
                    mma16816(acc[hh][nt], a0l, a1l, a2l, a3l, b10, b11);
                }
            }
            den[hh][0] += dsum0;
            den[hh][1] += dsum1;
        }
    }

    // ---- epilogue: out = acc / den + bias ----
    const int gr0 = b * N_ + i0 + wid * 16 + q;
#pragma unroll
    for (int hh = 0; hh < 2; hh++) {
        float d0 = den[hh][0];
        d0 += __shfl_xor_sync(0xffffffffu, d0, 1);
        d0 += __shfl_xor_sync(0xffffffffu, d0, 2);
        float d1 = den[hh][1];
        d1 += __shfl_xor_sync(0xffffffffu, d1, 1);
        d1 += __shfl_xor_sync(0xffffffffu, d1, 2);
        const float rl0 = 1.0f / d0, rl1 = 1.0f / d1;
#pragma unroll
        for (int nt = 0; nt < 8; nt++) {
            const int col = (hp * 2 + hh) * 64 + nt * 8 + c * 2;
            float2 bv = __ldg((const float2*)(bias + col));
            float2 o0, o1;
            o0.x = acc[hh][nt][0] * rl0 + bv.x;
            o0.y = acc[hh][nt][1] * rl0 + bv.y;
            o1.x = acc[hh][nt][2] * rl1 + bv.x;
            o1.y = acc[hh][nt][3] * rl1 + bv.y;
            *(float2*)(out + (size_t)gr0 * OUT_ + col)       = o0;
            *(float2*)(out + (size_t)(gr0 + 8) * OUT_ + col) = o1;
        }
    }
}

// ============================================================================
extern "C" void kernel_launch(void* const* d_in, const int* in_sizes, int n_in,
                              void* d_out, int out_size)
{
    const float* x     = (const float*)d_in[0];
    const float* adj   = (const float*)d_in[1];
    const float* W     = (const float*)d_in[2];
    const float* a_src = (const float*)d_in[3];
    const float* a_dst = (const float*)d_in[4];
    const float* bias  = (const float*)d_in[5];
    float* out = (float*)d_out;

    gemm_h_kernel<<<dim3(H_, (B_ * N_) / 64), 256>>>(x, W, a_src, a_dst);
    gat_attn_mma_kernel<<<dim3(N_ / 128, B_, 2), 256>>>(adj, bias, out);
}

// round 9
// speedup vs baseline: 2.1072x; 1.1144x over previous
#include <cuda_runtime.h>
#include <cuda_bf16.h>
#include <cstdint>

#define B_   16
#define N_   1024
#define DIN_ 256
#define H_   4
#define F_   64
#define OUT_ 256

// -------- scratch (device globals) --------
__device__ float    g_h[B_ * N_ * OUT_];        // h fp32 row-major
__device__ float    g_esrc[B_ * H_ * N_];
__device__ float    g_edst[B_ * H_ * N_];
// hT[b][hd][f][j] as bf16 pairs (uint32): hi and lo splits
__device__ uint32_t g_hT1[B_ * H_ * F_ * (N_ / 2)];
__device__ uint32_t g_hT2[B_ * H_ * F_ * (N_ / 2)];

// bf16 split helpers
__device__ __forceinline__ uint32_t hi_pack(float v0, float v1) {
    uint32_t r;
    asm("prmt.b32 %0, %1, %2, 0x7632;" : "=r"(r)
        : "r"(__float_as_uint(v0)), "r"(__float_as_uint(v1)));
    return r;
}
__device__ __forceinline__ uint32_t lo_pack(float v0, float v1) {
    float l0 = v0 - __uint_as_float(__float_as_uint(v0) & 0xFFFF0000u);
    float l1 = v1 - __uint_as_float(__float_as_uint(v1) & 0xFFFF0000u);
    uint32_t r;
    asm("cvt.rn.bf16x2.f32 %0, %1, %2;" : "=r"(r) : "f"(l1), "f"(l0));
    return r;
}

// warp-level bf16 MMA (HMMA path, sm_80+)
__device__ __forceinline__ void mma16816(float* c, uint32_t a0, uint32_t a1,
                                         uint32_t a2, uint32_t a3,
                                         uint32_t b0, uint32_t b1) {
    asm volatile(
        "mma.sync.aligned.m16n8k16.row.col.f32.bf16.bf16.f32 "
        "{%0,%1,%2,%3}, {%4,%5,%6,%7}, {%8,%9}, {%0,%1,%2,%3};"
        : "+f"(c[0]), "+f"(c[1]), "+f"(c[2]), "+f"(c[3])
        : "r"(a0), "r"(a1), "r"(a2), "r"(a3), "r"(b0), "r"(b1));
}

// ============================================================================
// Kernel 1: h = x @ W via split-bf16 HMMA.
// CTA = 128 rows x 128 cols (2 heads); grid (128, 2); 8 warps.
// Warp w: rows w*16..+15, all 128 cols (16 n8-tiles). 3-term split mma.
// Epilogue: h fp32 store + fused e_src/e_dst reductions.
// ============================================================================
__global__ __launch_bounds__(256, 2) void gemm_h_mma_kernel(
    const float* __restrict__ x, const float* __restrict__ W,
    const float* __restrict__ a_src, const float* __restrict__ a_dst)
{
    __shared__ uint32_t sxh[128 * 12];   // x hi words, stride 12 (conflict-free frags)
    __shared__ uint32_t sxl[128 * 12];   // x lo words
    __shared__ uint4    swt[128 * 4];    // W^T packed frags {bh0,bh1,bl0,bl1} per (f, c)
    __shared__ float    sAs[256];
    __shared__ float    sAd[256];

    const int tid = threadIdx.x;
    const int wid = tid >> 5;
    const int l   = tid & 31;
    const int q   = l >> 2;
    const int c   = l & 3;
    const int R0  = blockIdx.x * 128;
    const int F0  = blockIdx.y * 128;

    if (tid < 256) { sAs[tid] = a_src[tid]; sAd[tid] = a_dst[tid]; }

    float acc[16][4];
#pragma unroll
    for (int nt = 0; nt < 16; nt++)
#pragma unroll
        for (int k = 0; k < 4; k++) acc[nt][k] = 0.f;

    const int xr = tid >> 1, xh = tid & 1;   // x-stage mapping
    const int wf = tid >> 1, wh = tid & 1;   // W-stage mapping

    for (int kt = 0; kt < 16; kt++) {
        __syncthreads();
        // stage x tile (rows R0..R0+127, k = kt*16..+15) as hi/lo bf16 pairs
        {
            const float* xp = x + (size_t)(R0 + xr) * DIN_ + kt * 16 + xh * 8;
            float4 a = *(const float4*)xp;
            float4 b = *(const float4*)(xp + 4);
            uint4 hi = make_uint4(hi_pack(a.x, a.y), hi_pack(a.z, a.w),
                                  hi_pack(b.x, b.y), hi_pack(b.z, b.w));
            uint4 lo = make_uint4(lo_pack(a.x, a.y), lo_pack(a.z, a.w),
                                  lo_pack(b.x, b.y), lo_pack(b.z, b.w));
            *(uint4*)&sxh[xr * 12 + xh * 4] = hi;
            *(uint4*)&sxl[xr * 12 + xh * 4] = lo;
        }
        // stage W^T packed fragments: swt[f][cc] = {bh(k2c),bh(k2c+8),bl(k2c),bl(k2c+8)}
        {
#pragma unroll
            for (int t = 0; t < 2; t++) {
                int cc = wh * 2 + t;
                const float* wp = W + (size_t)(kt * 16 + 2 * cc) * OUT_ + F0 + wf;
                float w0 = wp[0];
                float w1 = wp[OUT_];
                float w2 = wp[8 * OUT_];
                float w3 = wp[9 * OUT_];
                swt[wf * 4 + cc] = make_uint4(hi_pack(w0, w1), hi_pack(w2, w3),
                                              lo_pack(w0, w1), lo_pack(w2, w3));
            }
        }
        __syncthreads();

        const int r0 = wid * 16 + q;
        const uint32_t ah0 = sxh[r0 * 12 + c];
        const uint32_t ah1 = sxh[(r0 + 8) * 12 + c];
        const uint32_t ah2 = sxh[r0 * 12 + c + 4];
        const uint32_t ah3 = sxh[(r0 + 8) * 12 + c + 4];
        const uint32_t al0 = sxl[r0 * 12 + c];
        const uint32_t al1 = sxl[(r0 + 8) * 12 + c];
        const uint32_t al2 = sxl[r0 * 12 + c + 4];
        const uint32_t al3 = sxl[(r0 + 8) * 12 + c + 4];

#pragma unroll
        for (int nt = 0; nt < 16; nt++) {
            uint4 v = swt[(nt * 8 + q) * 4 + c];
            mma16816(acc[nt], ah0, ah1, ah2, ah3, v.x, v.y);
            mma16816(acc[nt], ah0, ah1, ah2, ah3, v.z, v.w);
            mma16816(acc[nt], al0, al1, al2, al3, v.x, v.y);
        }
    }

    // ---- epilogue: store h fp32 + e_src/e_dst reductions ----
    const int gr0 = R0 + wid * 16 + q;
#pragma unroll
    for (int nt = 0; nt < 16; nt++) {
        const int gc = F0 + nt * 8 + 2 * c;
        *(float2*)(g_h + (size_t)gr0 * OUT_ + gc)       = make_float2(acc[nt][0], acc[nt][1]);
        *(float2*)(g_h + (size_t)(gr0 + 8) * OUT_ + gc) = make_float2(acc[nt][2], acc[nt][3]);
    }

    const int b = gr0 >> 10;
    const int n = gr0 & (N_ - 1);
#pragma unroll
    for (int hh = 0; hh < 2; hh++) {
        float ps0 = 0.f, ps1 = 0.f, pd0 = 0.f, pd1 = 0.f;
#pragma unroll
        for (int t = 0; t < 8; t++) {
            const int nt = hh * 8 + t;
            const int gc = F0 + nt * 8 + 2 * c;
            float2 as2 = *(float2*)&sAs[gc];
            float2 ad2 = *(float2*)&sAd[gc];
            ps0 += acc[nt][0] * as2.x + acc[nt][1] * as2.y;
            ps1 += acc[nt][2] * as2.x + acc[nt][3] * as2.y;
            pd0 += acc[nt][0] * ad2.x + acc[nt][1] * ad2.y;
            pd1 += acc[nt][2] * ad2.x + acc[nt][3] * ad2.y;
        }
#pragma unroll
        for (int off = 1; off <= 2; off <<= 1) {
            ps0 += __shfl_xor_sync(0xffffffffu, ps0, off);
            ps1 += __shfl_xor_sync(0xffffffffu, ps1, off);
            pd0 += __shfl_xor_sync(0xffffffffu, pd0, off);
            pd1 += __shfl_xor_sync(0xffffffffu, pd1, off);
        }
        if (c == 0) {
            const int hd = blockIdx.y * 2 + hh;
            g_esrc[(b * H_ + hd) * N_ + n]     = ps0;
            g_esrc[(b * H_ + hd) * N_ + n + 8] = ps1;
            g_edst[(b * H_ + hd) * N_ + n]     = pd0;
            g_edst[(b * H_ + hd) * N_ + n + 8] = pd1;
        }
    }
}

// ============================================================================
// Kernel 1b: transpose + split h -> g_hT1/g_hT2 (proven repack pattern).
// CTA = one (b, 64-j block, head); grid 1024.
// ============================================================================
__global__ __launch_bounds__(256) void transpose_split_kernel()
{
    __shared__ float h_t[64 * 65];

    const int bid = blockIdx.x;
    const int hd  = bid & 3;
    const int jb  = (bid >> 2) & 15;
    const int b   = bid >> 6;
    const int tid = threadIdx.x;

    for (int idx = tid; idx < 1024; idx += 256) {
        int j  = idx >> 4;
        int f4 = idx & 15;
        float4 v = *(const float4*)(g_h + (size_t)(b * N_ + jb * 64 + j) * OUT_ + hd * 64 + f4 * 4);
        h_t[(f4 * 4 + 0) * 65 + j] = v.x;
        h_t[(f4 * 4 + 1) * 65 + j] = v.y;
        h_t[(f4 * 4 + 2) * 65 + j] = v.z;
        h_t[(f4 * 4 + 3) * 65 + j] = v.w;
    }
    __syncthreads();

    const int f  = tid >> 2;
    const int nq = (tid & 3) * 16;
    const float* row = &h_t[f * 65 + nq];
    uint32_t hi[8], lo[8];
#pragma unroll
    for (int k = 0; k < 8; k++) {
        hi[k] = hi_pack(row[2 * k], row[2 * k + 1]);
        lo[k] = lo_pack(row[2 * k], row[2 * k + 1]);
    }
    size_t bi = ((size_t)((b * H_ + hd) * F_ + f)) * (N_ / 2) + (jb * 64 + nq) / 2;
    *(uint4*)&g_hT1[bi]     = make_uint4(hi[0], hi[1], hi[2], hi[3]);
    *(uint4*)&g_hT1[bi + 4] = make_uint4(hi[4], hi[5], hi[6], hi[7]);
    *(uint4*)&g_hT2[bi]     = make_uint4(lo[0], lo[1], lo[2], lo[3]);
    *(uint4*)&g_hT2[bi + 4] = make_uint4(lo[4], lo[5], lo[6], lo[7]);
}

// ============================================================================
// Kernel 2: HMMA flash-GAT, head-split, uint4-packed B fragments.
// CTA = (b, 128 i-rows, 2 heads); grid.z = 2; 8 warps.
// hbi element = {b1_c, b1_c+4, b2_c, b2_c+4}: one LDS.128 per nt per kt.
// Row stride 36 uint4 (== 4 mod 8 -> per-quarter-warp bank-distinct).
// ============================================================================
#define HBI_STR 36

__global__ __launch_bounds__(256, 2) void gat_attn_mma_kernel(
    const float* __restrict__ adj, const float* __restrict__ bias,
    float* __restrict__ out)
{
    __shared__ uint32_t abits[128][4];
    __shared__ float    es_sh[2][128];
    __shared__ float    ed_sh[2][128];
    __shared__ uint4    hbi[64 * HBI_STR];

    const int tid = threadIdx.x;
    const int wid = tid >> 5;
    const int l   = tid & 31;
    const int q   = l >> 2;
    const int c   = l & 3;
    const int b   = blockIdx.y;
    const int i0  = blockIdx.x * 128;
    const int hp  = blockIdx.z;          // head pair: heads hp*2, hp*2+1

    for (int idx = tid; idx < 2 * 128; idx += 256)
        ed_sh[idx >> 7][idx & 127] =
            g_edst[(b * H_ + hp * 2 + (idx >> 7)) * N_ + i0 + (idx & 127)];

    float acc[2][8][4];
    float den[2][2];
#pragma unroll
    for (int hh = 0; hh < 2; hh++) {
        den[hh][0] = 0.f; den[hh][1] = 0.f;
#pragma unroll
        for (int nt = 0; nt < 8; nt++)
#pragma unroll
            for (int k = 0; k < 4; k++) acc[hh][nt][k] = 0.f;
    }

    const float* adj_b = adj + (size_t)b * N_ * N_;

    for (int chunk = 0; chunk < 8; chunk++) {
        const int j0 = chunk * 128;
        __syncthreads();

        // adjacency bitmask: warp w handles its own 16 rows
#pragma unroll 4
        for (int k = 0; k < 16; k++) {
            int r = wid * 16 + k;
            const float* arow = adj_b + (size_t)(i0 + r) * N_ + j0;
#pragma unroll
            for (int jg = 0; jg < 4; jg++) {
                uint32_t m = __ballot_sync(0xffffffffu, arow[jg * 32 + l] > 0.5f);
                if (l == 0) abits[r][jg] = m;
            }
        }
        for (int idx = tid; idx < 2 * 128; idx += 256)
            es_sh[idx >> 7][idx & 127] =
                g_esrc[(b * H_ + hp * 2 + (idx >> 7)) * N_ + j0 + (idx & 127)];

#pragma unroll
        for (int hh = 0; hh < 2; hh++) {
            __syncthreads();
            // stage packed B fragments for this head
            {
                const size_t gb = ((size_t)(b * H_ + hp * 2 + hh) * F_ + (tid >> 2)) * (N_ / 2)
                                  + chunk * 64;
                const int f = tid >> 2;
#pragma unroll
                for (int t = 0; t < 2; t++) {
                    const int kt = (tid & 3) * 2 + t;
                    uint32_t v1[8], v2[8];
                    *(uint4*)&v1[0] = *(const uint4*)&g_hT1[gb + kt * 8];
                    *(uint4*)&v1[4] = *(const uint4*)&g_hT1[gb + kt * 8 + 4];
                    *(uint4*)&v2[0] = *(const uint4*)&g_hT2[gb + kt * 8];
                    *(uint4*)&v2[4] = *(const uint4*)&g_hT2[gb + kt * 8 + 4];
#pragma unroll
                    for (int cc = 0; cc < 4; cc++)
                        hbi[f * HBI_STR + kt * 4 + cc] =
                            make_uint4(v1[cc], v1[cc + 4], v2[cc], v2[cc + 4]);
                }
            }
            __syncthreads();

            const int r0 = wid * 16 + q;
            const float ed0 = ed_sh[hh][r0];
            const float ed1 = ed_sh[hh][r0 + 8];
            float dsum0 = 0.f, dsum1 = 0.f;
#pragma unroll
            for (int kt = 0; kt < 8; kt++) {
                const int jA = kt * 16 + c * 2;
                float2 eA = *(const float2*)&es_sh[hh][jA];
                float2 eB = *(const float2*)&es_sh[hh][jA + 8];
                const uint32_t w0 = abits[r0][kt >> 1];
                const uint32_t w1 = abits[r0 + 8][kt >> 1];
                const int bb = ((kt & 1) << 4) + c * 2;

                float p00, p01, p08, p09, p10, p11, p18, p19;
                {
                    float s;
                    s = ed0 + eA.x; s = fmaxf(s, 0.2f * s); p00 = ((w0 >> bb) & 1u) ? __expf(s) : 0.f;
                    s = ed0 + eA.y; s = fmaxf(s, 0.2f * s); p01 = ((w0 >> (bb + 1)) & 1u) ? __expf(s) : 0.f;
                    s = ed0 + eB.x; s = fmaxf(s, 0.2f * s); p08 = ((w0 >> (bb + 8)) & 1u) ? __expf(s) : 0.f;
                    s = ed0 + eB.y; s = fmaxf(s, 0.2f * s); p09 = ((w0 >> (bb + 9)) & 1u) ? __expf(s) : 0.f;
                    s = ed1 + eA.x; s = fmaxf(s, 0.2f * s); p10 = ((w1 >> bb) & 1u) ? __expf(s) : 0.f;
                    s = ed1 + eA.y; s = fmaxf(s, 0.2f * s); p11 = ((w1 >> (bb + 1)) & 1u) ? __expf(s) : 0.f;
                    s = ed1 + eB.x; s = fmaxf(s, 0.2f * s); p18 = ((w1 >> (bb + 8)) & 1u) ? __expf(s) : 0.f;
                    s = ed1 + eB.y; s = fmaxf(s, 0.2f * s); p19 = ((w1 >> (bb + 9)) & 1u) ? __expf(s) : 0.f;
                }
                dsum0 += (p00 + p01) + (p08 + p09);
                dsum1 += (p10 + p11) + (p18 + p19);

                const uint32_t a0h = hi_pack(p00, p01), a1h = hi_pack(p10, p11);
                const uint32_t a2h = hi_pack(p08, p09), a3h = hi_pack(p18, p19);
                const uint32_t a0l = lo_pack(p00, p01), a1l = lo_pack(p10, p11);
                const uint32_t a2l = lo_pack(p08, p09), a3l = lo_pack(p18, p19);

#pragma unroll
                for (int nt = 0; nt < 8; nt++) {
                    uint4 v = hbi[(nt * 8 + q) * HBI_STR + kt * 4 + c];
                    mma16816(acc[hh][nt], a0h, a1h, a2h, a3h, v.x, v.y);
                    mma16816(acc[hh][nt], a0h, a1h, a2h, a3h, v.z, v.w);
                    mma16816(acc[hh][nt], a0l, a1l, a2l, a3l, v.x, v.y);
                }
            }
            den[hh][0] += dsum0;
            den[hh][1] += dsum1;
        }
    }

    // ---- epilogue: out = acc / den + bias ----
    const int gr0 = b * N_ + i0 + wid * 16 + q;
#pragma unroll
    for (int hh = 0; hh < 2; hh++) {
        float d0 = den[hh][0];
        d0 += __shfl_xor_sync(0xffffffffu, d0, 1);
        d0 += __shfl_xor_sync(0xffffffffu, d0, 2);
        float d1 = den[hh][1];
        d1 += __shfl_xor_sync(0xffffffffu, d1, 1);
        d1 += __shfl_xor_sync(0xffffffffu, d1, 2);
        const float rl0 = 1.0f / d0, rl1 = 1.0f / d1;
#pragma unroll
        for (int nt = 0; nt < 8; nt++) {
            const int col = (hp * 2 + hh) * 64 + nt * 8 + c * 2;
            float2 bv = __ldg((const float2*)(bias + col));
            float2 o0, o1;
            o0.x = acc[hh][nt][0] * rl0 + bv.x;
            o0.y = acc[hh][nt][1] * rl0 + bv.y;
            o1.x = acc[hh][nt][2] * rl1 + bv.x;
            o1.y = acc[hh][nt][3] * rl1 + bv.y;
            *(float2*)(out + (size_t)gr0 * OUT_ + col)       = o0;
            *(float2*)(out + (size_t)(gr0 + 8) * OUT_ + col) = o1;
        }
    }
}

// ============================================================================
extern "C" void kernel_launch(void* const* d_in, const int* in_sizes, int n_in,
                              void* d_out, int out_size)
{
    const float* x     = (const float*)d_in[0];
    const float* adj   = (const float*)d_in[1];
    const float* W     = (const float*)d_in[2];
    const float* a_src = (const float*)d_in[3];
    const float* a_dst = (const float*)d_in[4];
    const float* bias  = (const float*)d_in[5];
    float* out = (float*)d_out;

    gemm_h_mma_kernel<<<dim3((B_ * N_) / 128, 2), 256>>>(x, W, a_src, a_dst);
    transpose_split_kernel<<<B_ * 16 * H_, 256>>>();
    gat_attn_mma_kernel<<<dim3(N_ / 128, B_, 2), 256>>>(adj, bias, out);
}